// round 10
// baseline (speedup 1.0000x reference)
#include <cuda_runtime.h>
#include <cuda_fp16.h>

// Problem constants: N=100000, E=1600000, IN_C=16, HID=32, HEADS=2
#define MAXN 100000
#define MAXE 1600000
#define NEG 0.2f
#define INV_TEMP (1.0f / 0.7f)

// ---- device scratch (static; no allocations allowed) ----
__device__ __align__(16) __half g_xp[MAXN * 64];   // [N][64] projected features (fp16)
__device__ float g_asrc[MAXN * 2];                 // attention src logits per head
__device__ float g_adst[MAXN * 2];                 // attention dst logits per head
__device__ __align__(16) __half g_ps[MAXN * 32];   // h @ w1[0:32,:]  (fp16)
__device__ __align__(16) __half g_pd[MAXN * 32];   // h @ w1[32:64,:] (fp16)
__device__ __align__(16) int2 g_edge[MAXE];        // packed (src, dst)
__device__ __align__(16) int g_srcs[MAXE];         // CSR: src ids grouped by dst
__device__ __align__(16) int g_deg[MAXN + 4];      // in-degree histogram
__device__ int g_off[MAXN + 1];                    // CSR offsets
__device__ int g_cur[MAXN];                        // scatter cursors
__device__ int g_bsum[128];                        // scan block totals
__device__ int g_bflag[128];                       // scan publish flags
__device__ int g_is64;

// K_init: zero histogram (vectorized) + scan flags; detect edge int width
__global__ void k_init(const int* __restrict__ ei_words, int nVec) {
    int i = blockIdx.x * blockDim.x + threadIdx.x;
    if (i < nVec) ((uint4*)g_deg)[i] = make_uint4(0, 0, 0, 0);
    if (i < 128) g_bflag[i] = 0;
    if (i == 0) {
        int nonzero = 0;
        #pragma unroll
        for (int j = 0; j < 64; j++)
            if (ei_words[2 * j + 1] != 0) nonzero++;
        g_is64 = (nonzero == 0) ? 1 : 0;
    }
}

// K0b: pack edges to int2 and build in-degree histogram. 2 edges per thread
// with vector loads; one int4 store covers both packed edges.
__global__ void k0_pack(const void* __restrict__ ei, int E) {
    int e = 2 * (blockIdx.x * blockDim.x + threadIdx.x);
    if (e >= E) return;
    int s0, d0, s1 = 0, d1 = 0;
    bool two = (e + 1) < E;
    if (g_is64) {
        const long long* p = (const long long*)ei;
        if (two) {
            longlong2 sv = *(const longlong2*)(p + e);
            longlong2 dv = *(const longlong2*)(p + E + e);
            s0 = (int)sv.x; s1 = (int)sv.y;
            d0 = (int)dv.x; d1 = (int)dv.y;
        } else {
            s0 = (int)p[e]; d0 = (int)p[E + e];
        }
    } else {
        const int* p = (const int*)ei;
        if (two) {
            int2 sv = *(const int2*)(p + e);
            int2 dv = *(const int2*)(p + E + e);
            s0 = sv.x; s1 = sv.y;
            d0 = dv.x; d1 = dv.y;
        } else {
            s0 = p[e]; d0 = p[E + e];
        }
    }
    if (two) {
        *(int4*)(g_edge + e) = make_int4(s0, d0, s1, d1);
        atomicAdd(&g_deg[d0], 1);
        atomicAdd(&g_deg[d1], 1);
    } else {
        g_edge[e] = make_int2(s0, d0);
        atomicAdd(&g_deg[d0], 1);
    }
}

// K_scan: single-kernel exclusive scan of g_deg -> g_off (+ cursor init,
// sentinel). Warp-shuffle block scan; cross-block base via parallel lookback
// (all <=98 blocks co-resident, so the spin always progresses).
__global__ void __launch_bounds__(1024) k_scan(int N, int E) {
    __shared__ int warpsums[32];
    __shared__ int sred[32];
    __shared__ int sbase;
    const unsigned FULL = 0xFFFFFFFFu;
    int tid = threadIdx.x;
    int lane = tid & 31, wid = tid >> 5;
    int b = blockIdx.x;
    int i = b * 1024 + tid;

    int v = (i < N) ? g_deg[i] : 0;
    int sc = v;
    #pragma unroll
    for (int ofs = 1; ofs < 32; ofs <<= 1) {
        int t = __shfl_up_sync(FULL, sc, ofs);
        if (lane >= ofs) sc += t;
    }
    if (lane == 31) warpsums[wid] = sc;
    __syncthreads();
    if (wid == 0) {
        int w = warpsums[lane];
        #pragma unroll
        for (int ofs = 1; ofs < 32; ofs <<= 1) {
            int t = __shfl_up_sync(FULL, w, ofs);
            if (lane >= ofs) w += t;
        }
        warpsums[lane] = w;
    }
    __syncthreads();
    int blockpref = (wid > 0) ? warpsums[wid - 1] : 0;
    int excl = sc + blockpref - v;
    int total = warpsums[31];

    if (tid == 0) {
        g_bsum[b] = total;
        __threadfence();
        atomicExch(&g_bflag[b], 1);
    }

    int part = 0;
    if (tid < b) {
        while (atomicAdd(&g_bflag[tid], 0) == 0) { }
        __threadfence();
        part = g_bsum[tid];
    }
    #pragma unroll
    for (int ofs = 16; ofs > 0; ofs >>= 1)
        part += __shfl_xor_sync(FULL, part, ofs);
    if (lane == 0) sred[wid] = part;
    __syncthreads();
    if (tid == 0) {
        int s = 0;
        #pragma unroll
        for (int k = 0; k < 4; k++) s += sred[k];
        sbase = s;
    }
    __syncthreads();
    int base = sbase;

    if (i < N) {
        int o = excl + base;
        g_off[i] = o;
        g_cur[i] = o;
    }
    if (b == 0 && tid == 0) g_off[N] = E;
}

// K_fused: blocks [0, nodeBlocks) do node projection (chunked, low-reg); the
// rest scatter edges (4 edges/thread -> 4 independent atomic chains in flight).
__global__ void __launch_bounds__(256, 4) k_fused_scatter_node(
    const float* __restrict__ x, const float* __restrict__ W,
    const float* __restrict__ att_src, const float* __restrict__ att_dst,
    int N, int E, int nodeBlocks) {
    int tid = threadIdx.x;

    if (blockIdx.x >= (unsigned)nodeBlocks) {
        // ---- edge scatter: 4 consecutive edges per thread ----
        int e = ((blockIdx.x - nodeBlocks) * blockDim.x + tid) * 4;
        if (e >= E) return;
        if (e + 4 <= E) {
            int4 p01 = *(const int4*)(g_edge + e);       // (s0,d0,s1,d1)
            int4 p23 = *(const int4*)(g_edge + e + 2);   // (s2,d2,s3,d3)
            int q0 = atomicAdd(&g_cur[p01.y], 1);
            int q1 = atomicAdd(&g_cur[p01.w], 1);
            int q2 = atomicAdd(&g_cur[p23.y], 1);
            int q3 = atomicAdd(&g_cur[p23.w], 1);
            g_srcs[q0] = p01.x;
            g_srcs[q1] = p01.z;
            g_srcs[q2] = p23.x;
            g_srcs[q3] = p23.z;
        } else {
            for (; e < E; e++) {
                int2 sd = g_edge[e];
                int pos = atomicAdd(&g_cur[sd.y], 1);
                g_srcs[pos] = sd.x;
            }
        }
        return;
    }

    // ---- node projection part (chunked, 16 output columns at a time) ----
    __shared__ float sW[16 * 64];
    __shared__ float sAs[64];
    __shared__ float sAd[64];
    for (int i = tid; i < 16 * 64; i += blockDim.x) sW[i] = W[i];
    if (tid < 64) { sAs[tid] = att_src[tid]; sAd[tid] = att_dst[tid]; }
    __syncthreads();

    int n = blockIdx.x * blockDim.x + tid;
    if (n >= N) return;

    float xv[16];
    const float4* x4 = (const float4*)(x + (size_t)n * 16);
    #pragma unroll
    for (int i = 0; i < 4; i++) {
        float4 t = x4[i];
        xv[4 * i + 0] = t.x; xv[4 * i + 1] = t.y;
        xv[4 * i + 2] = t.z; xv[4 * i + 3] = t.w;
    }

    float hs[2] = {0.f, 0.f};
    float hd[2] = {0.f, 0.f};
    uint4* xpo = (uint4*)(g_xp + (size_t)n * 64);

    #pragma unroll
    for (int ch = 0; ch < 4; ch++) {
        float v[16];
        float as = 0.f, ad = 0.f;
        #pragma unroll
        for (int jj = 0; jj < 16; jj++) {
            int j = ch * 16 + jj;
            float acc = 0.f;
            #pragma unroll
            for (int k = 0; k < 16; k++) acc = fmaf(xv[k], sW[k * 64 + j], acc);
            v[jj] = acc;
            as = fmaf(sAs[j], acc, as);
            ad = fmaf(sAd[j], acc, ad);
        }
        int hh = ch >> 1;
        hs[hh] += as;
        hd[hh] += ad;
        union { uint4 u; __half2 p[4]; } pk;
        #pragma unroll
        for (int g = 0; g < 2; g++) {
            #pragma unroll
            for (int j = 0; j < 4; j++)
                pk.p[j] = __floats2half2_rn(v[8 * g + 2 * j], v[8 * g + 2 * j + 1]);
            xpo[2 * ch + g] = pk.u;
        }
    }

    g_asrc[n * 2 + 0] = hs[0]; g_asrc[n * 2 + 1] = hs[1];
    g_adst[n * 2 + 0] = hd[0]; g_adst[n * 2 + 1] = hd[1];
}

// K2b3: warp-per-destination GAT aggregation + fused MLP layer-1 fold.
// PERSISTENT grid: w1 staged to shared once per block (592 blocks), warps
// stride over nodes.
__global__ void __launch_bounds__(256) k2b3_aggregate(const float* __restrict__ bias,
                                                      const float* __restrict__ w1, int N) {
    __shared__ float sW1[64 * 32];
    int tid = threadIdx.x;
    for (int i = tid; i < 64 * 32; i += blockDim.x) sW1[i] = w1[i];
    __syncthreads();

    int c = tid & 31;
    int h = c >> 4;
    int c15 = c & 15;
    const unsigned FULL = 0xFFFFFFFFu;
    float bias0 = __ldg(&bias[2 * c15]);
    float bias1 = __ldg(&bias[2 * c15 + 1]);

    int warpId = (blockIdx.x * blockDim.x + tid) >> 5;
    int nWarps = (gridDim.x * blockDim.x) >> 5;

    for (int n = warpId; n < N; n += nWarps) {
        float adn = g_adst[n * 2 + h];
        float ee = g_asrc[n * 2 + h] + adn;           // self loop
        ee = ee > 0.f ? ee : NEG * ee;
        float w = __expf(ee);
        float2 xs = __half22float2(*(const __half2*)(g_xp + (size_t)n * 64 + 2 * c));
        float acc0 = w * xs.x, acc1 = w * xs.y, dsum = w;

        int i = g_off[n];
        int end = g_off[n + 1];

        for (; i + 8 <= end; i += 8) {
            int s[8];
            #pragma unroll
            for (int j = 0; j < 8; j++) s[j] = __ldg(&g_srcs[i + j]);
            float a[8];
            __half2 xh[8];
            #pragma unroll
            for (int j = 0; j < 8; j++) {
                a[j] = __ldg(&g_asrc[s[j] * 2 + h]);
                xh[j] = *(const __half2*)(g_xp + (size_t)s[j] * 64 + 2 * c);
            }
            #pragma unroll
            for (int j = 0; j < 8; j++) {
                float e0 = a[j] + adn; e0 = e0 > 0.f ? e0 : NEG * e0;
                float w0 = __expf(e0);
                dsum += w0;
                float2 f = __half22float2(xh[j]);
                acc0 = fmaf(w0, f.x, acc0);
                acc1 = fmaf(w0, f.y, acc1);
            }
        }
        for (; i + 2 <= end; i += 2) {
            int s0 = __ldg(&g_srcs[i]), s1 = __ldg(&g_srcs[i + 1]);
            float a0 = __ldg(&g_asrc[s0 * 2 + h]);
            float a1 = __ldg(&g_asrc[s1 * 2 + h]);
            __half2 x0 = *(const __half2*)(g_xp + (size_t)s0 * 64 + 2 * c);
            __half2 x1 = *(const __half2*)(g_xp + (size_t)s1 * 64 + 2 * c);
            float e0 = a0 + adn; e0 = e0 > 0.f ? e0 : NEG * e0;
            float e1 = a1 + adn; e1 = e1 > 0.f ? e1 : NEG * e1;
            float w0 = __expf(e0), w1v = __expf(e1);
            dsum += w0 + w1v;
            float2 f0 = __half22float2(x0);
            float2 f1 = __half22float2(x1);
            acc0 = fmaf(w0, f0.x, acc0);  acc1 = fmaf(w0, f0.y, acc1);
            acc0 = fmaf(w1v, f1.x, acc0); acc1 = fmaf(w1v, f1.y, acc1);
        }
        if (i < end) {
            int s = __ldg(&g_srcs[i]);
            float a = __ldg(&g_asrc[s * 2 + h]);
            __half2 xh = *(const __half2*)(g_xp + (size_t)s * 64 + 2 * c);
            float e0 = a + adn; e0 = e0 > 0.f ? e0 : NEG * e0;
            float w0 = __expf(e0);
            dsum += w0;
            float2 f = __half22float2(xh);
            acc0 = fmaf(w0, f.x, acc0);
            acc1 = fmaf(w0, f.y, acc1);
        }

        float d0 = __shfl_sync(FULL, dsum, 0);
        float d1 = __shfl_sync(FULL, dsum, 16);
        float p0 = __shfl_sync(FULL, acc0, (c + 16) & 31);
        float p1 = __shfl_sync(FULL, acc1, (c + 16) & 31);

        float h0 = 0.5f * (acc0 / d0 + p0 / d1) + bias0;
        float h1 = 0.5f * (acc1 / d0 + p1 / d1) + bias1;

        // fused k3: ps/pd = h @ w1 (lane c computes output channel c)
        float ps = 0.f, pd = 0.f;
        #pragma unroll
        for (int k = 0; k < 16; k++) {
            float ha = __shfl_sync(FULL, h0, k);
            float hb = __shfl_sync(FULL, h1, k);
            ps = fmaf(ha, sW1[(2 * k) * 32 + c], ps);
            ps = fmaf(hb, sW1[(2 * k + 1) * 32 + c], ps);
            pd = fmaf(ha, sW1[(32 + 2 * k) * 32 + c], pd);
            pd = fmaf(hb, sW1[(32 + 2 * k + 1) * 32 + c], pd);
        }
        g_ps[(size_t)n * 32 + c] = __float2half_rn(ps);
        g_pd[(size_t)n * 32 + c] = __float2half_rn(pd);
    }
}

// K4: per-edge MLP. 4-lane group per consecutive edge pair (one int4 edge
// load); two independent pairs in flight per thread. ps+pd summed in half2.
__device__ __forceinline__ float mlp_quarter(const uint4 a, const uint4 b,
                                             const float* b1r, const float* w2r) {
    union { uint4 u; __half2 hh[4]; } ua, ub;
    ua.u = a; ub.u = b;
    float acc = 0.f;
    #pragma unroll
    for (int j = 0; j < 4; j++) {
        __half2 s = __hadd2(ua.hh[j], ub.hh[j]);
        float2 f = __half22float2(s);
        float h0 = fmaxf(f.x + b1r[2 * j], 0.f);
        float h1 = fmaxf(f.y + b1r[2 * j + 1], 0.f);
        acc = fmaf(h0, w2r[2 * j], acc);
        acc = fmaf(h1, w2r[2 * j + 1], acc);
    }
    return acc;
}

__global__ void __launch_bounds__(256) k4_edge_mlp(const float* __restrict__ b1,
                                                   const float* __restrict__ w2,
                                                   const float* __restrict__ b2,
                                                   float* __restrict__ out, int E) {
    int tid = blockIdx.x * blockDim.x + threadIdx.x;
    int q = tid & 3;
    float b1r[8], w2r[8];
    #pragma unroll
    for (int i = 0; i < 8; i++) {
        b1r[i] = __ldg(&b1[q * 8 + i]);
        w2r[i] = __ldg(&w2[q * 8 + i]);
    }
    float b2v = __ldg(&b2[0]);
    const unsigned FULL = 0xFFFFFFFFu;

    int nGroups = (gridDim.x * blockDim.x) >> 2;
    int nPairs = (E + 1) >> 1;

    for (int p = tid >> 2; p < nPairs; p += 2 * nGroups) {
        int pB = p + nGroups;
        bool hasB = pB < nPairs;
        int eA = 2 * p, eB = 2 * pB;

        int4 edA = __ldg((const int4*)(g_edge + eA));
        int4 edB = hasB ? __ldg((const int4*)(g_edge + eB)) : make_int4(0, 0, 0, 0);

        uint4 psA0 = *((const uint4*)(g_ps + (size_t)edA.x * 32) + q);
        uint4 pdA0 = *((const uint4*)(g_pd + (size_t)edA.y * 32) + q);
        uint4 psA1 = *((const uint4*)(g_ps + (size_t)edA.z * 32) + q);
        uint4 pdA1 = *((const uint4*)(g_pd + (size_t)edA.w * 32) + q);
        uint4 psB0 = *((const uint4*)(g_ps + (size_t)edB.x * 32) + q);
        uint4 pdB0 = *((const uint4*)(g_pd + (size_t)edB.y * 32) + q);
        uint4 psB1 = *((const uint4*)(g_ps + (size_t)edB.z * 32) + q);
        uint4 pdB1 = *((const uint4*)(g_pd + (size_t)edB.w * 32) + q);

        float vA0 = mlp_quarter(psA0, pdA0, b1r, w2r);
        float vA1 = mlp_quarter(psA1, pdA1, b1r, w2r);
        float vB0 = mlp_quarter(psB0, pdB0, b1r, w2r);
        float vB1 = mlp_quarter(psB1, pdB1, b1r, w2r);

        float a0 = vA0 + __shfl_xor_sync(FULL, vA0, 1);
        float a1 = vA1 + __shfl_xor_sync(FULL, vA1, 1);
        float mA = (q & 1) ? a1 : a0;
        mA += __shfl_xor_sync(FULL, mA, 2);

        float c0 = vB0 + __shfl_xor_sync(FULL, vB0, 1);
        float c1 = vB1 + __shfl_xor_sync(FULL, vB1, 1);
        float mB = (q & 1) ? c1 : c0;
        mB += __shfl_xor_sync(FULL, mB, 2);

        if (q < 2) {
            int e = eA + q;
            if (e < E) out[e] = (mA + b2v) * INV_TEMP;
            if (hasB) {
                int e2 = eB + q;
                if (e2 < E) out[e2] = (mB + b2v) * INV_TEMP;
            }
        }
    }
}

extern "C" void kernel_launch(void* const* d_in, const int* in_sizes, int n_in,
                              void* d_out, int out_size) {
    const float* x        = (const float*)d_in[0];
    const void*  ei       = d_in[1];
    const float* W        = (const float*)d_in[2];
    const float* att_src  = (const float*)d_in[3];
    const float* att_dst  = (const float*)d_in[4];
    const float* bias     = (const float*)d_in[5];
    const float* w1       = (const float*)d_in[6];
    const float* b1       = (const float*)d_in[7];
    const float* w2       = (const float*)d_in[8];
    const float* b2       = (const float*)d_in[9];
    float* out = (float*)d_out;

    int N = in_sizes[0] / 16;  // x is [N, 16]
    int E = in_sizes[1] / 2;   // edge_index is [2, E]
    int NB = (N + 1023) / 1024;
    int nodeBlocks = (N + 255) / 256;
    int edgeBlocks4 = (E + 1023) / 1024;       // 4 edges per thread
    int packBlocks = (E + 511) / 512;          // 2 edges per thread
    int nVec = (N + 3) / 4;

    k_init<<<(nVec + 255) / 256, 256>>>((const int*)ei, nVec);
    k0_pack<<<packBlocks, 256>>>(ei, E);
    k_scan<<<NB, 1024>>>(N, E);
    k_fused_scatter_node<<<nodeBlocks + edgeBlocks4, 256>>>(x, W, att_src, att_dst,
                                                            N, E, nodeBlocks);
    {
        long long T = (long long)N * 32;
        k2b3_aggregate<<<592, 256>>>(bias, w1, N);
    }
    k4_edge_mlp<<<1184, 256>>>(b1, w2, b2, out, E);
}

// round 11
// speedup vs baseline: 1.0534x; 1.0534x over previous
#include <cuda_runtime.h>
#include <cuda_fp16.h>

// Problem constants: N=100000, E=1600000, IN_C=16, HID=32, HEADS=2
#define MAXN 100000
#define MAXE 1600000
#define NEG 0.2f
#define INV_TEMP (1.0f / 0.7f)

// ---- device scratch (static; no allocations allowed) ----
__device__ __align__(16) __half g_xp[MAXN * 64];   // [N][64] projected features (fp16)
__device__ float g_asrc[MAXN * 2];                 // attention src logits per head
__device__ float g_adst[MAXN * 2];                 // attention dst logits per head
__device__ __align__(16) __half g_ps[MAXN * 32];   // h @ w1[0:32,:]  (fp16)
__device__ __align__(16) __half g_pd[MAXN * 32];   // h @ w1[32:64,:] (fp16)
__device__ __align__(16) int2 g_edge[MAXE];        // packed (src, dst)
__device__ __align__(16) int g_rank[MAXE];         // rank of edge within its dst group
__device__ __align__(16) int g_srcs[MAXE];         // CSR: src ids grouped by dst
__device__ int g_deg[MAXN];                        // in-degree histogram
__device__ int g_off[MAXN + 1];                    // CSR offsets
__device__ int g_bsum[128];                        // scan block totals
__device__ int g_bflag[128];                       // scan publish flags
__device__ int g_is64;

// K_init: zero histogram + scan flags; thread 0 detects edge int width
__global__ void k_init(const int* __restrict__ ei_words, int N) {
    int i = blockIdx.x * blockDim.x + threadIdx.x;
    if (i < N) g_deg[i] = 0;
    if (i < 128) g_bflag[i] = 0;
    if (i == 0) {
        int nonzero = 0;
        #pragma unroll
        for (int j = 0; j < 64; j++)
            if (ei_words[2 * j + 1] != 0) nonzero++;
        g_is64 = (nonzero == 0) ? 1 : 0;
    }
}

// K0b: pack edges to int2, build in-degree histogram, and record each edge's
// rank within its destination group (the atomicAdd return value — free).
__global__ void k0_pack(const void* __restrict__ ei, int E) {
    int e = blockIdx.x * blockDim.x + threadIdx.x;
    if (e >= E) return;
    int s, d;
    if (g_is64) {
        const long long* p = (const long long*)ei;
        s = (int)p[e];
        d = (int)p[e + E];
    } else {
        const int* p = (const int*)ei;
        s = p[e];
        d = p[e + E];
    }
    g_edge[e] = make_int2(s, d);
    g_rank[e] = atomicAdd(&g_deg[d], 1);
}

// K_scan: single-kernel exclusive scan of g_deg -> g_off (+ sentinel).
// Warp-shuffle block scan; cross-block base via parallel lookback (all <=98
// blocks co-resident, so the spin always progresses).
__global__ void __launch_bounds__(1024) k_scan(int N, int E) {
    __shared__ int warpsums[32];
    __shared__ int sred[32];
    __shared__ int sbase;
    const unsigned FULL = 0xFFFFFFFFu;
    int tid = threadIdx.x;
    int lane = tid & 31, wid = tid >> 5;
    int b = blockIdx.x;
    int i = b * 1024 + tid;

    int v = (i < N) ? g_deg[i] : 0;
    int sc = v;
    #pragma unroll
    for (int ofs = 1; ofs < 32; ofs <<= 1) {
        int t = __shfl_up_sync(FULL, sc, ofs);
        if (lane >= ofs) sc += t;
    }
    if (lane == 31) warpsums[wid] = sc;
    __syncthreads();
    if (wid == 0) {
        int w = warpsums[lane];
        #pragma unroll
        for (int ofs = 1; ofs < 32; ofs <<= 1) {
            int t = __shfl_up_sync(FULL, w, ofs);
            if (lane >= ofs) w += t;
        }
        warpsums[lane] = w;
    }
    __syncthreads();
    int blockpref = (wid > 0) ? warpsums[wid - 1] : 0;
    int excl = sc + blockpref - v;
    int total = warpsums[31];

    if (tid == 0) {
        g_bsum[b] = total;
        __threadfence();
        atomicExch(&g_bflag[b], 1);
    }

    int part = 0;
    if (tid < b) {
        while (atomicAdd(&g_bflag[tid], 0) == 0) { }
        __threadfence();
        part = g_bsum[tid];
    }
    #pragma unroll
    for (int ofs = 16; ofs > 0; ofs >>= 1)
        part += __shfl_xor_sync(FULL, part, ofs);
    if (lane == 0) sred[wid] = part;
    __syncthreads();
    if (tid == 0) {
        int s = 0;
        #pragma unroll
        for (int k = 0; k < 4; k++) s += sred[k];
        sbase = s;
    }
    __syncthreads();
    int base = sbase;

    if (i < N) g_off[i] = excl + base;
    if (b == 0 && tid == 0) g_off[N] = E;
}

// K_fused: blocks [0, nodeBlocks) do node projection (chunked, low-reg); the
// rest scatter edges WITHOUT atomics: pos = g_off[dst] + precomputed rank.
__global__ void __launch_bounds__(256, 4) k_fused_scatter_node(
    const float* __restrict__ x, const float* __restrict__ W,
    const float* __restrict__ att_src, const float* __restrict__ att_dst,
    int N, int E, int nodeBlocks) {
    int tid = threadIdx.x;

    if (blockIdx.x >= (unsigned)nodeBlocks) {
        // ---- edge scatter: 2 consecutive edges per thread, no atomics ----
        int e = ((blockIdx.x - nodeBlocks) * blockDim.x + tid) * 2;
        if (e >= E) return;
        if (e + 2 <= E) {
            int4 p01 = *(const int4*)(g_edge + e);   // (s0,d0,s1,d1)
            int2 r01 = *(const int2*)(g_rank + e);
            int o0 = __ldg(&g_off[p01.y]);
            int o1 = __ldg(&g_off[p01.w]);
            g_srcs[o0 + r01.x] = p01.x;
            g_srcs[o1 + r01.y] = p01.z;
        } else {
            int2 sd = g_edge[e];
            g_srcs[__ldg(&g_off[sd.y]) + g_rank[e]] = sd.x;
        }
        return;
    }

    // ---- node projection part (chunked, 16 output columns at a time) ----
    __shared__ float sW[16 * 64];
    __shared__ float sAs[64];
    __shared__ float sAd[64];
    for (int i = tid; i < 16 * 64; i += blockDim.x) sW[i] = W[i];
    if (tid < 64) { sAs[tid] = att_src[tid]; sAd[tid] = att_dst[tid]; }
    __syncthreads();

    int n = blockIdx.x * blockDim.x + tid;
    if (n >= N) return;

    float xv[16];
    const float4* x4 = (const float4*)(x + (size_t)n * 16);
    #pragma unroll
    for (int i = 0; i < 4; i++) {
        float4 t = x4[i];
        xv[4 * i + 0] = t.x; xv[4 * i + 1] = t.y;
        xv[4 * i + 2] = t.z; xv[4 * i + 3] = t.w;
    }

    float hs[2] = {0.f, 0.f};
    float hd[2] = {0.f, 0.f};
    uint4* xpo = (uint4*)(g_xp + (size_t)n * 64);

    #pragma unroll
    for (int ch = 0; ch < 4; ch++) {
        float v[16];
        float as = 0.f, ad = 0.f;
        #pragma unroll
        for (int jj = 0; jj < 16; jj++) {
            int j = ch * 16 + jj;
            float acc = 0.f;
            #pragma unroll
            for (int k = 0; k < 16; k++) acc = fmaf(xv[k], sW[k * 64 + j], acc);
            v[jj] = acc;
            as = fmaf(sAs[j], acc, as);
            ad = fmaf(sAd[j], acc, ad);
        }
        int hh = ch >> 1;
        hs[hh] += as;
        hd[hh] += ad;
        union { uint4 u; __half2 p[4]; } pk;
        #pragma unroll
        for (int g = 0; g < 2; g++) {
            #pragma unroll
            for (int j = 0; j < 4; j++)
                pk.p[j] = __floats2half2_rn(v[8 * g + 2 * j], v[8 * g + 2 * j + 1]);
            xpo[2 * ch + g] = pk.u;
        }
    }

    g_asrc[n * 2 + 0] = hs[0]; g_asrc[n * 2 + 1] = hs[1];
    g_adst[n * 2 + 0] = hd[0]; g_adst[n * 2 + 1] = hd[1];
}

// K2b3: warp-per-destination GAT aggregation + fused MLP layer-1 fold.
// One warp per node (R9 configuration — max warps for latency hiding).
__global__ void __launch_bounds__(256) k2b3_aggregate(const float* __restrict__ bias,
                                                      const float* __restrict__ w1, int N) {
    __shared__ float sW1[64 * 32];
    int tid = threadIdx.x;
    for (int i = tid; i < 64 * 32; i += blockDim.x) sW1[i] = w1[i];
    __syncthreads();

    int n = (blockIdx.x * blockDim.x + tid) >> 5;
    if (n >= N) return;
    int c = tid & 31;
    int h = c >> 4;
    const unsigned FULL = 0xFFFFFFFFu;

    float adn = g_adst[n * 2 + h];
    float ee = g_asrc[n * 2 + h] + adn;           // self loop
    ee = ee > 0.f ? ee : NEG * ee;
    float w = __expf(ee);
    float2 xs = __half22float2(*(const __half2*)(g_xp + (size_t)n * 64 + 2 * c));
    float acc0 = w * xs.x, acc1 = w * xs.y, dsum = w;

    int i = g_off[n];
    int end = g_off[n + 1];

    for (; i + 8 <= end; i += 8) {
        int s[8];
        #pragma unroll
        for (int j = 0; j < 8; j++) s[j] = __ldg(&g_srcs[i + j]);
        float a[8];
        __half2 xh[8];
        #pragma unroll
        for (int j = 0; j < 8; j++) {
            a[j] = __ldg(&g_asrc[s[j] * 2 + h]);
            xh[j] = *(const __half2*)(g_xp + (size_t)s[j] * 64 + 2 * c);
        }
        #pragma unroll
        for (int j = 0; j < 8; j++) {
            float e0 = a[j] + adn; e0 = e0 > 0.f ? e0 : NEG * e0;
            float w0 = __expf(e0);
            dsum += w0;
            float2 f = __half22float2(xh[j]);
            acc0 = fmaf(w0, f.x, acc0);
            acc1 = fmaf(w0, f.y, acc1);
        }
    }
    for (; i + 2 <= end; i += 2) {
        int s0 = __ldg(&g_srcs[i]), s1 = __ldg(&g_srcs[i + 1]);
        float a0 = __ldg(&g_asrc[s0 * 2 + h]);
        float a1 = __ldg(&g_asrc[s1 * 2 + h]);
        __half2 x0 = *(const __half2*)(g_xp + (size_t)s0 * 64 + 2 * c);
        __half2 x1 = *(const __half2*)(g_xp + (size_t)s1 * 64 + 2 * c);
        float e0 = a0 + adn; e0 = e0 > 0.f ? e0 : NEG * e0;
        float e1 = a1 + adn; e1 = e1 > 0.f ? e1 : NEG * e1;
        float w0 = __expf(e0), w1v = __expf(e1);
        dsum += w0 + w1v;
        float2 f0 = __half22float2(x0);
        float2 f1 = __half22float2(x1);
        acc0 = fmaf(w0, f0.x, acc0);  acc1 = fmaf(w0, f0.y, acc1);
        acc0 = fmaf(w1v, f1.x, acc0); acc1 = fmaf(w1v, f1.y, acc1);
    }
    if (i < end) {
        int s = __ldg(&g_srcs[i]);
        float a = __ldg(&g_asrc[s * 2 + h]);
        __half2 xh = *(const __half2*)(g_xp + (size_t)s * 64 + 2 * c);
        float e0 = a + adn; e0 = e0 > 0.f ? e0 : NEG * e0;
        float w0 = __expf(e0);
        dsum += w0;
        float2 f = __half22float2(xh);
        acc0 = fmaf(w0, f.x, acc0);
        acc1 = fmaf(w0, f.y, acc1);
    }

    float d0 = __shfl_sync(FULL, dsum, 0);
    float d1 = __shfl_sync(FULL, dsum, 16);
    float p0 = __shfl_sync(FULL, acc0, (c + 16) & 31);
    float p1 = __shfl_sync(FULL, acc1, (c + 16) & 31);

    int c15 = c & 15;
    float h0 = 0.5f * (acc0 / d0 + p0 / d1) + __ldg(&bias[2 * c15]);
    float h1 = 0.5f * (acc1 / d0 + p1 / d1) + __ldg(&bias[2 * c15 + 1]);

    // fused k3: ps/pd = h @ w1 (lane c computes output channel c)
    float ps = 0.f, pd = 0.f;
    #pragma unroll
    for (int k = 0; k < 16; k++) {
        float ha = __shfl_sync(FULL, h0, k);
        float hb = __shfl_sync(FULL, h1, k);
        ps = fmaf(ha, sW1[(2 * k) * 32 + c], ps);
        ps = fmaf(hb, sW1[(2 * k + 1) * 32 + c], ps);
        pd = fmaf(ha, sW1[(32 + 2 * k) * 32 + c], pd);
        pd = fmaf(hb, sW1[(32 + 2 * k + 1) * 32 + c], pd);
    }
    g_ps[(size_t)n * 32 + c] = __float2half_rn(ps);
    g_pd[(size_t)n * 32 + c] = __float2half_rn(pd);
}

// K4: per-edge MLP. 4-lane group per consecutive edge pair (one int4 edge
// load); two independent pairs in flight per thread. ps+pd summed in half2.
__device__ __forceinline__ float mlp_quarter(const uint4 a, const uint4 b,
                                             const float* b1r, const float* w2r) {
    union { uint4 u; __half2 hh[4]; } ua, ub;
    ua.u = a; ub.u = b;
    float acc = 0.f;
    #pragma unroll
    for (int j = 0; j < 4; j++) {
        __half2 s = __hadd2(ua.hh[j], ub.hh[j]);
        float2 f = __half22float2(s);
        float h0 = fmaxf(f.x + b1r[2 * j], 0.f);
        float h1 = fmaxf(f.y + b1r[2 * j + 1], 0.f);
        acc = fmaf(h0, w2r[2 * j], acc);
        acc = fmaf(h1, w2r[2 * j + 1], acc);
    }
    return acc;
}

__global__ void __launch_bounds__(256) k4_edge_mlp(const float* __restrict__ b1,
                                                   const float* __restrict__ w2,
                                                   const float* __restrict__ b2,
                                                   float* __restrict__ out, int E) {
    int tid = blockIdx.x * blockDim.x + threadIdx.x;
    int q = tid & 3;
    float b1r[8], w2r[8];
    #pragma unroll
    for (int i = 0; i < 8; i++) {
        b1r[i] = __ldg(&b1[q * 8 + i]);
        w2r[i] = __ldg(&w2[q * 8 + i]);
    }
    float b2v = __ldg(&b2[0]);
    const unsigned FULL = 0xFFFFFFFFu;

    int nGroups = (gridDim.x * blockDim.x) >> 2;
    int nPairs = (E + 1) >> 1;

    for (int p = tid >> 2; p < nPairs; p += 2 * nGroups) {
        int pB = p + nGroups;
        bool hasB = pB < nPairs;
        int eA = 2 * p, eB = 2 * pB;

        int4 edA = __ldg((const int4*)(g_edge + eA));
        int4 edB = hasB ? __ldg((const int4*)(g_edge + eB)) : make_int4(0, 0, 0, 0);

        uint4 psA0 = *((const uint4*)(g_ps + (size_t)edA.x * 32) + q);
        uint4 pdA0 = *((const uint4*)(g_pd + (size_t)edA.y * 32) + q);
        uint4 psA1 = *((const uint4*)(g_ps + (size_t)edA.z * 32) + q);
        uint4 pdA1 = *((const uint4*)(g_pd + (size_t)edA.w * 32) + q);
        uint4 psB0 = *((const uint4*)(g_ps + (size_t)edB.x * 32) + q);
        uint4 pdB0 = *((const uint4*)(g_pd + (size_t)edB.y * 32) + q);
        uint4 psB1 = *((const uint4*)(g_ps + (size_t)edB.z * 32) + q);
        uint4 pdB1 = *((const uint4*)(g_pd + (size_t)edB.w * 32) + q);

        float vA0 = mlp_quarter(psA0, pdA0, b1r, w2r);
        float vA1 = mlp_quarter(psA1, pdA1, b1r, w2r);
        float vB0 = mlp_quarter(psB0, pdB0, b1r, w2r);
        float vB1 = mlp_quarter(psB1, pdB1, b1r, w2r);

        float a0 = vA0 + __shfl_xor_sync(FULL, vA0, 1);
        float a1 = vA1 + __shfl_xor_sync(FULL, vA1, 1);
        float mA = (q & 1) ? a1 : a0;
        mA += __shfl_xor_sync(FULL, mA, 2);

        float c0 = vB0 + __shfl_xor_sync(FULL, vB0, 1);
        float c1 = vB1 + __shfl_xor_sync(FULL, vB1, 1);
        float mB = (q & 1) ? c1 : c0;
        mB += __shfl_xor_sync(FULL, mB, 2);

        if (q < 2) {
            int e = eA + q;
            if (e < E) out[e] = (mA + b2v) * INV_TEMP;
            if (hasB) {
                int e2 = eB + q;
                if (e2 < E) out[e2] = (mB + b2v) * INV_TEMP;
            }
        }
    }
}

extern "C" void kernel_launch(void* const* d_in, const int* in_sizes, int n_in,
                              void* d_out, int out_size) {
    const float* x        = (const float*)d_in[0];
    const void*  ei       = d_in[1];
    const float* W        = (const float*)d_in[2];
    const float* att_src  = (const float*)d_in[3];
    const float* att_dst  = (const float*)d_in[4];
    const float* bias     = (const float*)d_in[5];
    const float* w1       = (const float*)d_in[6];
    const float* b1       = (const float*)d_in[7];
    const float* w2       = (const float*)d_in[8];
    const float* b2       = (const float*)d_in[9];
    float* out = (float*)d_out;

    int N = in_sizes[0] / 16;  // x is [N, 16]
    int E = in_sizes[1] / 2;   // edge_index is [2, E]
    int NB = (N + 1023) / 1024;
    int nodeBlocks = (N + 255) / 256;
    int edgeBlocks2 = (E + 511) / 512;   // 2 edges per thread in scatter

    k_init<<<(N + 255) / 256, 256>>>((const int*)ei, N);
    k0_pack<<<(E + 255) / 256, 256>>>(ei, E);
    k_scan<<<NB, 1024>>>(N, E);
    k_fused_scatter_node<<<nodeBlocks + edgeBlocks2, 256>>>(x, W, att_src, att_dst,
                                                            N, E, nodeBlocks);
    {
        long long T = (long long)N * 32;
        k2b3_aggregate<<<(unsigned)((T + 255) / 256), 256>>>(bias, w1, N);
    }
    k4_edge_mlp<<<1184, 256>>>(b1, w2, b2, out, E);
}